// round 11
// baseline (speedup 1.0000x reference)
#include <cuda_runtime.h>
#include <math.h>

// Problem constants
#define B_   256
#define T_   200
#define H_   256
#define G3   768       // 3*H
#define VO   50001     // V+1

typedef unsigned long long ull;

// ---------------- device scratch (no allocs allowed) ----------------
__device__ float    g_gx[(size_t)B_ * T_ * G3];   // 157 MB gates_x
__device__ float    g_h[2][B_ * H_];              // double-buffered hidden state
__device__ unsigned g_cnt;                        // grid barrier count (returns to 0)
__device__ unsigned g_gen;                        // grid barrier generation
__device__ int      g_is64;                       // input_ids dtype flag

// ---------------- packed f32x2 helpers ----------------
__device__ __forceinline__ ull ffma2(ull a, ull b, ull c) {
    ull d;
    asm("fma.rn.f32x2 %0, %1, %2, %3;" : "=l"(d) : "l"(a), "l"(b), "l"(c));
    return d;
}
__device__ __forceinline__ ull packf2(float lo, float hi) {
    ull u;
    asm("mov.b64 %0, {%1, %2};" : "=l"(u) : "f"(lo), "f"(hi));
    return u;
}
__device__ __forceinline__ float sumf2(ull u) {
    float lo, hi;
    asm("mov.b64 {%0, %1}, %2;" : "=f"(lo), "=f"(hi) : "l"(u));
    return lo + hi;
}
__device__ __forceinline__ float sigmoidf_(float x) {
    return 1.0f / (1.0f + expf(-x));
}

// Core inner product: one SMEM row (per-lane) against 8 broadcast SMEM rows
// (stride 260 floats), K=256, packed pairs along K.
__device__ __forceinline__ void dot8(const float* __restrict__ a,
                                     const float* __restrict__ w0,
                                     ull acc[8]) {
#pragma unroll 4
    for (int k = 0; k < H_; k += 4) {
        ulonglong2 hv = *reinterpret_cast<const ulonglong2*>(a + k);
#pragma unroll
        for (int c = 0; c < 8; ++c) {
            ulonglong2 wv = *reinterpret_cast<const ulonglong2*>(w0 + c * 260 + k);
            acc[c] = ffma2(hv.x, wv.x, acc[c]);
            acc[c] = ffma2(hv.y, wv.y, acc[c]);
        }
    }
}

// ---------------- software grid barrier (all CTAs resident) ----------------
__device__ __forceinline__ void grid_sync_(unsigned nb) {
    __syncthreads();
    if (threadIdx.x == 0) {
        volatile unsigned* genp = &g_gen;
        unsigned gen = *genp;
        __threadfence();
        if (atomicAdd(&g_cnt, 1u) == nb - 1u) {
            g_cnt = 0u;
            __threadfence();
            atomicAdd(&g_gen, 1u);
        } else {
            while (*genp == gen) { }
            __threadfence();
        }
    }
    __syncthreads();
}

// ---------------- dtype detect: int64 vs int32 input_ids ----------------
__global__ void detect_kernel(const unsigned* idw) {
    __shared__ int any;
    if (threadIdx.x == 0) any = 0;
    __syncthreads();
    int local = 0;
    for (int i = threadIdx.x; i < 2048; i += blockDim.x)
        if (idw[2 * i + 1] != 0u) local = 1;
    if (local) atomicOr(&any, 1);
    __syncthreads();
    if (threadIdx.x == 0) g_is64 = (any == 0) ? 1 : 0;
}

// ---------------- phase 1: gates_x = emb[ids] @ w_ih + b_ih ----------------
// CTA = 32 t-rows (one batch element) x 64 gate-cols.
// grid = (12 col tiles, 7 t tiles, 256 batch). Early-exit past length.
__global__ void __launch_bounds__(256) gates_kernel(const void* __restrict__ ids_raw,
                                                    const int* __restrict__ lengths,
                                                    const float* __restrict__ emb,
                                                    const float* __restrict__ w_ih,
                                                    const float* __restrict__ b_ih) {
    extern __shared__ float sm[];
    float (*x_s)[260] = (float(*)[260])sm;              // 32 x 260
    float (*w_s)[260] = (float(*)[260])(sm + 32 * 260); // 64 x 260

    const int b   = blockIdx.z;
    const int len = lengths[b];
    const int t0  = blockIdx.y * 32;
    if (t0 >= len) return;
    const int gc0 = blockIdx.x * 64;
    const int tid = threadIdx.x;
    const int is64 = g_is64;

    // gather x tile (rows = emb[ids[b, t0+r]])
    for (int i = tid; i < 32 * 64; i += 256) {
        int r = i >> 6, q = i & 63;
        int t = t0 + r;
        if (t < T_) {
            long long ofs = (long long)b * T_ + t;
            long long id = is64 ? ((const long long*)ids_raw)[ofs]
                                : (long long)((const int*)ids_raw)[ofs];
            reinterpret_cast<float4*>(&x_s[r][0])[q] =
                __ldg(reinterpret_cast<const float4*>(emb + id * H_) + q);
        }
    }
    // load w_ih column slice: w_s[c][k] = w_ih[k*768 + gc0 + c]
    for (int i = tid; i < 64 * H_; i += 256) {
        int c = i & 63, k = i >> 6;
        w_s[c][k] = w_ih[k * G3 + gc0 + c];
    }
    __syncthreads();

    const int lane = tid & 31, wp = tid >> 5;
    const int c0 = wp * 8;
    ull acc[8];
#pragma unroll
    for (int c = 0; c < 8; ++c) acc[c] = packf2(b_ih[gc0 + c0 + c], 0.f);

    dot8(&x_s[lane][0], &w_s[c0][0], acc);

    const int t = t0 + lane;
    if (t < len) {
        float* outp = g_gx + ((long long)b * T_ + t) * G3 + gc0 + c0;
        float4 o0 = make_float4(sumf2(acc[0]), sumf2(acc[1]), sumf2(acc[2]), sumf2(acc[3]));
        float4 o1 = make_float4(sumf2(acc[4]), sumf2(acc[5]), sumf2(acc[6]), sumf2(acc[7]));
        *reinterpret_cast<float4*>(outp)     = o0;
        *reinterpret_cast<float4*>(outp + 4) = o1;
    }
}

// ---------------- phase 2: persistent GRU recurrence ----------------
// grid = (16 unit tiles x 8 batch tiles) = 128 CTAs, 192 threads (6 warps).
// CTA owns batch rows b0..b0+31 and hidden units u0..u0+15 (48 w_hh cols in SMEM,
// persistent across all 200 steps). One software grid barrier per step.
#define NB_REC 128u
__global__ void __launch_bounds__(192) rec_kernel(const int* __restrict__ lengths,
                                                  const float* __restrict__ w_hh,
                                                  const float* __restrict__ b_hh) {
    extern __shared__ float sm[];
    float (*w_s)[260]  = (float(*)[260])sm;                          // 48 x 260
    float (*h_s)[260]  = (float(*)[260])(sm + 48 * 260);             // 32 x 260
    float (*rec_s)[49] = (float(*)[49]) (sm + (48 + 32) * 260);      // 32 x 49
    float (*gxh_s)[16] = (float(*)[16]) (sm + (48 + 32) * 260 + 32 * 49); // 32 x 16
    __shared__ int len_s[32];

    const int u0  = blockIdx.x * 16;
    const int b0  = blockIdx.y * 32;
    const int tid = threadIdx.x;
    const int lane = tid & 31, wp = tid / 32;   // wp 0..5
    const int c0 = wp * 8;
    const int g  = c0 >> 4;                     // gate id: 0,0,1,1,2,2
    const int uoff = c0 & 15;
    const bool isZR = (wp < 4);

    // persistent weight slice: w_s[c][k] = w_hh[k*768 + gate*256 + u0 + u]
    for (int i = tid; i < 48 * H_; i += 192) {
        int c = i % 48, k = i / 48;
        int gg = c >> 4, u = c & 15;
        w_s[c][k] = w_hh[k * G3 + gg * H_ + u0 + u];
    }
    if (tid < 32) len_s[tid] = lengths[b0 + tid];

    float bias[8];
#pragma unroll
    for (int c = 0; c < 8; ++c) {
        int cl = c0 + c;
        bias[c] = b_hh[(cl >> 4) * H_ + u0 + (cl & 15)];
    }

    // zero owned region of h buffer 0
    for (int i = tid; i < 512; i += 192) {
        int r = i >> 4, u = i & 15;
        g_h[0][(b0 + r) * H_ + u0 + u] = 0.f;
    }
    grid_sync_(NB_REC);

    int cur = 0;
    for (int t = 0; t < T_; ++t) {
        const float* hc = g_h[cur];
        float* hn = g_h[cur ^ 1];

        // prefetch this step's gx (z/r gates) for this lane's row
        float gxv[8];
        if (isZR) {
            const float* gp = g_gx + ((long long)(b0 + lane) * T_ + t) * G3 + g * H_ + u0 + uoff;
            float4 a = __ldg((const float4*)gp);
            float4 b4 = __ldg((const float4*)(gp + 4));
            gxv[0]=a.x; gxv[1]=a.y; gxv[2]=a.z; gxv[3]=a.w;
            gxv[4]=b4.x; gxv[5]=b4.y; gxv[6]=b4.z; gxv[7]=b4.w;
        } else {
#pragma unroll
            for (int c = 0; c < 8; ++c) gxv[c] = 0.f;
        }

        // load h tile (cross-SM data: must bypass L1 -> __ldcg)
        for (int i = tid; i < 32 * 64; i += 192) {
            int r = i >> 6, q = i & 63;
            *reinterpret_cast<float4*>(&h_s[r][q * 4]) =
                __ldcg(reinterpret_cast<const float4*>(hc + (b0 + r) * H_ + q * 4));
        }
        // stage gx for h-candidate gate (needed un-summed at combine)
        for (int i = tid; i < 512; i += 192) {
            int r = i >> 4, u = i & 15;
            gxh_s[r][u] = __ldg(g_gx + ((long long)(b0 + r) * T_ + t) * G3 + 2 * H_ + u0 + u);
        }
        __syncthreads();

        ull acc[8];
#pragma unroll
        for (int c = 0; c < 8; ++c) acc[c] = packf2(bias[c] + gxv[c], 0.f);

        dot8(&h_s[lane][0], &w_s[c0][0], acc);

#pragma unroll
        for (int c = 0; c < 8; ++c) rec_s[lane][c0 + c] = sumf2(acc[c]);
        __syncthreads();

        // gate combine + masked h update
        for (int i = tid; i < 512; i += 192) {
            int r = i >> 4, u = i & 15;
            float z  = sigmoidf_(rec_s[r][u]);        // xz + rz
            float rr = sigmoidf_(rec_s[r][16 + u]);   // xr + rr
            float hh = tanhf(gxh_s[r][u] + rr * rec_s[r][32 + u]);
            float ho = h_s[r][u0 + u];
            float hv = z * ho + (1.0f - z) * hh;
            hn[(b0 + r) * H_ + u0 + u] = (t < len_s[r]) ? hv : ho;
        }
        grid_sync_(NB_REC);
        cur ^= 1;
    }
    // T_=200 even -> final state in g_h[0]
}

// ---------------- phase 3: logits = h_final @ emb.T ----------------
// CTA = 32 batch rows x 64 vocab; grid = (782, 8).
__global__ void __launch_bounds__(256) logits_kernel(const float* __restrict__ emb,
                                                     float* __restrict__ out) {
    extern __shared__ float sm[];
    float (*h_s)[260] = (float(*)[260])sm;              // 32 x 260
    float (*e_s)[260] = (float(*)[260])(sm + 32 * 260); // 64 x 260

    const int v0 = blockIdx.x * 64;
    const int b0 = blockIdx.y * 32;
    const int tid = threadIdx.x;
    const float* hf = g_h[0];

    for (int i = tid; i < 32 * 64; i += 256) {
        int r = i >> 6, q = i & 63;
        *reinterpret_cast<float4*>(&h_s[r][q * 4]) =
            *reinterpret_cast<const float4*>(hf + (b0 + r) * H_ + q * 4);
    }
    for (int i = tid; i < 64 * 64; i += 256) {
        int v = i >> 6, q = i & 63;
        int vg = min(v0 + v, VO - 1);
        *reinterpret_cast<float4*>(&e_s[v][q * 4]) =
            __ldg(reinterpret_cast<const float4*>(emb + (long long)vg * H_) + q);
    }
    __syncthreads();

    const int lane = tid & 31, wp = tid >> 5;
    const int c0 = wp * 8;
    ull acc[8];
#pragma unroll
    for (int c = 0; c < 8; ++c) acc[c] = 0ull;

    dot8(&h_s[lane][0], &e_s[c0][0], acc);

    float* orow = out + (long long)(b0 + lane) * VO;
#pragma unroll
    for (int c = 0; c < 8; ++c) {
        int v = v0 + c0 + c;
        if (v < VO) orow[v] = sumf2(acc[c]);
    }
}

// ---------------- launch ----------------
extern "C" void kernel_launch(void* const* d_in, const int* in_sizes, int n_in,
                              void* d_out, int out_size) {
    const void*  ids     = d_in[0];                  // int64 or int32 [B,T]
    const int*   lengths = (const int*)d_in[1];      // int32 [B]
    const float* emb     = (const float*)d_in[2];    // [V+1, H]
    const float* w_ih    = (const float*)d_in[3];    // [H, 3H]
    const float* w_hh    = (const float*)d_in[4];    // [H, 3H]
    const float* b_ih    = (const float*)d_in[5];    // [3H]
    const float* b_hh    = (const float*)d_in[6];    // [3H]
    float* out = (float*)d_out;

    const int SMEM_GATES  = (32 + 64) * 260 * 4;                       // 99840
    const int SMEM_REC    = (48 + 32) * 260 * 4 + 32 * 49 * 4 + 32 * 16 * 4; // 91520
    const int SMEM_LOGITS = (32 + 64) * 260 * 4;                       // 99840

    cudaFuncSetAttribute(gates_kernel,  cudaFuncAttributeMaxDynamicSharedMemorySize, SMEM_GATES);
    cudaFuncSetAttribute(rec_kernel,    cudaFuncAttributeMaxDynamicSharedMemorySize, SMEM_REC);
    cudaFuncSetAttribute(logits_kernel, cudaFuncAttributeMaxDynamicSharedMemorySize, SMEM_LOGITS);

    detect_kernel<<<1, 256>>>((const unsigned*)ids);

    gates_kernel<<<dim3(12, 7, B_), 256, SMEM_GATES>>>(ids, lengths, emb, w_ih, b_ih);

    rec_kernel<<<dim3(16, 8), 192, SMEM_REC>>>(lengths, w_hh, b_hh);

    logits_kernel<<<dim3((VO + 63) / 64, 8), 256, SMEM_LOGITS>>>(emb, out);
}

// round 14
// speedup vs baseline: 1.0416x; 1.0416x over previous
#include <cuda_runtime.h>
#include <math.h>

// Problem constants
#define B_   256
#define T_   200
#define H_   256
#define G3   768       // 3*H
#define VO   50001     // V+1

typedef unsigned long long ull;

// ---------------- device scratch (no allocs allowed) ----------------
__device__ float    g_gx[(size_t)B_ * T_ * G3];   // 157 MB gates_x
__device__ float    g_h[2][B_ * H_];              // double-buffered hidden state
__device__ unsigned g_cnt2[8 * 64];               // per-group barrier counters (256B stride)
__device__ unsigned g_gen2[8 * 64];               // per-group generations
__device__ int      g_is64;                       // input_ids dtype flag

// ---------------- packed f32x2 helpers ----------------
__device__ __forceinline__ ull ffma2(ull a, ull b, ull c) {
    ull d;
    asm("fma.rn.f32x2 %0, %1, %2, %3;" : "=l"(d) : "l"(a), "l"(b), "l"(c));
    return d;
}
__device__ __forceinline__ ull packf2(float lo, float hi) {
    ull u;
    asm("mov.b64 %0, {%1, %2};" : "=l"(u) : "f"(lo), "f"(hi));
    return u;
}
__device__ __forceinline__ void unpackf2(ull u, float& lo, float& hi) {
    asm("mov.b64 {%0, %1}, %2;" : "=f"(lo), "=f"(hi) : "l"(u));
}
__device__ __forceinline__ float sumf2(ull u) {
    float lo, hi; unpackf2(u, lo, hi);
    return lo + hi;
}
__device__ __forceinline__ float sigmoidf_(float x) {
    return 1.0f / (1.0f + expf(-x));
}

// 4x8 register-tile micro-kernel body: a = 4 row values, b = 8 col values
// (as 4 f32x2 pairs), acc[4][4] pairs over columns.
#define MICRO_4x8(av, b01, b23, acc)                                          \
    do {                                                                      \
        ull a0_ = packf2((av).x, (av).x), a1_ = packf2((av).y, (av).y);       \
        ull a2_ = packf2((av).z, (av).z), a3_ = packf2((av).w, (av).w);       \
        (acc)[0][0] = ffma2(a0_, (b01).x, (acc)[0][0]);                       \
        (acc)[0][1] = ffma2(a0_, (b01).y, (acc)[0][1]);                       \
        (acc)[0][2] = ffma2(a0_, (b23).x, (acc)[0][2]);                       \
        (acc)[0][3] = ffma2(a0_, (b23).y, (acc)[0][3]);                       \
        (acc)[1][0] = ffma2(a1_, (b01).x, (acc)[1][0]);                       \
        (acc)[1][1] = ffma2(a1_, (b01).y, (acc)[1][1]);                       \
        (acc)[1][2] = ffma2(a1_, (b23).x, (acc)[1][2]);                       \
        (acc)[1][3] = ffma2(a1_, (b23).y, (acc)[1][3]);                       \
        (acc)[2][0] = ffma2(a2_, (b01).x, (acc)[2][0]);                       \
        (acc)[2][1] = ffma2(a2_, (b01).y, (acc)[2][1]);                       \
        (acc)[2][2] = ffma2(a2_, (b23).x, (acc)[2][2]);                       \
        (acc)[2][3] = ffma2(a2_, (b23).y, (acc)[2][3]);                       \
        (acc)[3][0] = ffma2(a3_, (b01).x, (acc)[3][0]);                       \
        (acc)[3][1] = ffma2(a3_, (b01).y, (acc)[3][1]);                       \
        (acc)[3][2] = ffma2(a3_, (b23).x, (acc)[3][2]);                       \
        (acc)[3][3] = ffma2(a3_, (b23).y, (acc)[3][3]);                       \
    } while (0)

// ---------------- per-group software barrier (16 CTAs, all resident) --------
__device__ __forceinline__ void group_sync_(int gid) {
    __syncthreads();
    if (threadIdx.x == 0) {
        unsigned* cntp = &g_cnt2[gid * 64];
        volatile unsigned* genp = &g_gen2[gid * 64];
        unsigned gen = *genp;
        __threadfence();
        if (atomicAdd(cntp, 1u) == 15u) {
            *cntp = 0u;
            __threadfence();
            atomicAdd((unsigned*)&g_gen2[gid * 64], 1u);
        } else {
            while (*genp == gen) { }
            __threadfence();
        }
    }
    __syncthreads();
}

// ---------------- dtype detect: int64 vs int32 input_ids ----------------
__global__ void detect_kernel(const unsigned* idw) {
    __shared__ int any;
    if (threadIdx.x == 0) any = 0;
    __syncthreads();
    int local = 0;
    for (int i = threadIdx.x; i < 2048; i += blockDim.x)
        if (idw[2 * i + 1] != 0u) local = 1;
    if (local) atomicOr(&any, 1);
    __syncthreads();
    if (threadIdx.x == 0) g_is64 = (any == 0) ? 1 : 0;
}

// ---------------- phase 1: gates_x = emb[ids] @ w_ih + b_ih ----------------
// CTA = 32 t-rows (one batch element) x 128 gate-cols, 128 threads, K-chunked
// register-tiled SGEMM (thread = 4 rows x 8 cols). Early-exit past length.
__global__ void __launch_bounds__(128) gates_kernel(const void* __restrict__ ids_raw,
                                                    const int* __restrict__ lengths,
                                                    const float* __restrict__ emb,
                                                    const float* __restrict__ w_ih,
                                                    const float* __restrict__ b_ih) {
    __shared__ float xs[32][36];    // [k][m]
    __shared__ float ws[32][132];   // [k][n]
    __shared__ int   ids_s[32];

    const int b   = blockIdx.z;
    const int len = lengths[b];
    const int t0  = blockIdx.y * 32;
    if (t0 >= len) return;
    const int gc0 = blockIdx.x * 128;
    const int tid = threadIdx.x;
    const int is64 = g_is64;

    if (tid < 32) {
        int t = t0 + tid;
        long long id = 0;
        if (t < T_) {
            long long ofs = (long long)b * T_ + t;
            id = is64 ? ((const long long*)ids_raw)[ofs]
                      : (long long)((const int*)ids_raw)[ofs];
        }
        ids_s[tid] = (int)id;
    }

    const int tx = tid & 15, ty = tid >> 4;
    const int n0 = tx * 8, m0 = ty * 4;

    ull acc[4][4];
#pragma unroll
    for (int p = 0; p < 4; ++p) {
        float2 bp = *reinterpret_cast<const float2*>(b_ih + gc0 + n0 + 2 * p);
        ull bu = packf2(bp.x, bp.y);
#pragma unroll
        for (int m = 0; m < 4; ++m) acc[m][p] = bu;
    }

    for (int kc = 0; kc < 8; ++kc) {
        const int k0 = kc * 32;
        __syncthreads();
        // stage x chunk transposed: xs[k][m] = emb[id_m][k0+k]
        for (int i = tid; i < 256; i += 128) {
            int r = i >> 3, kq = i & 7;
            float4 v = __ldg(reinterpret_cast<const float4*>(
                emb + (long long)ids_s[r] * H_ + k0 + kq * 4));
            xs[kq * 4 + 0][r] = v.x; xs[kq * 4 + 1][r] = v.y;
            xs[kq * 4 + 2][r] = v.z; xs[kq * 4 + 3][r] = v.w;
        }
        // stage w chunk: ws[k][n] = w_ih[(k0+k)*768 + gc0+n]  (n contiguous)
        for (int i = tid; i < 1024; i += 128) {
            int k = i >> 5, nq = i & 31;
            float4 v = __ldg(reinterpret_cast<const float4*>(
                w_ih + (long long)(k0 + k) * G3 + gc0 + nq * 4));
            *reinterpret_cast<float4*>(&ws[k][nq * 4]) = v;
        }
        __syncthreads();
#pragma unroll 8
        for (int k = 0; k < 32; ++k) {
            float4 av = *reinterpret_cast<const float4*>(&xs[k][m0]);
            ulonglong2 b01 = *reinterpret_cast<const ulonglong2*>(&ws[k][n0]);
            ulonglong2 b23 = *reinterpret_cast<const ulonglong2*>(&ws[k][n0 + 4]);
            MICRO_4x8(av, b01, b23, acc);
        }
    }

#pragma unroll
    for (int mi = 0; mi < 4; ++mi) {
        int t = t0 + m0 + mi;
        if (t < len) {
            float* o = g_gx + ((long long)b * T_ + t) * G3 + gc0 + n0;
            ulonglong2 s0, s1;
            s0.x = acc[mi][0]; s0.y = acc[mi][1];
            s1.x = acc[mi][2]; s1.y = acc[mi][3];
            *reinterpret_cast<ulonglong2*>(o)     = s0;
            *reinterpret_cast<ulonglong2*>(o + 4) = s1;
        }
    }
}

// ---------------- phase 2: persistent GRU recurrence ----------------
// grid = (16 unit tiles x 8 batch groups) = 128 CTAs, 256 threads (8 warps,
// 6 cols each -> balanced SMSPs). Per-GROUP barrier (16 CTAs). gx for step
// t+1 prefetched into a double-buffered SMEM stage before the barrier.
__global__ void __launch_bounds__(256) rec_kernel(const int* __restrict__ lengths,
                                                  const float* __restrict__ w_hh,
                                                  const float* __restrict__ b_hh) {
    extern __shared__ float sm[];
    float (*w_s)[260]  = (float(*)[260])sm;                           // 48 x 260
    float (*h_s)[260]  = (float(*)[260])(sm + 48 * 260);              // 32 x 260
    float (*rec_s)[49] = (float(*)[49]) (sm + 80 * 260);              // 32 x 49
    float (*gx_b0)[49] = (float(*)[49]) (sm + 80 * 260 + 32 * 49);    // 32 x 49
    float (*gx_b1)[49] = (float(*)[49]) (sm + 80 * 260 + 64 * 49);    // 32 x 49
    __shared__ int len_s[32];

    const int u0  = blockIdx.x * 16;
    const int b0  = blockIdx.y * 32;
    const int gid = blockIdx.y;
    const int tid = threadIdx.x;
    const int lane = tid & 31, wp = tid >> 5;   // 8 warps
    const int c0 = wp * 6;                      // 6 cols per warp

    // persistent weight slice: w_s[c][k] = w_hh[k*768 + gate*256 + u0 + u]
    for (int i = tid; i < 48 * H_; i += 256) {
        int c = i % 48, k = i / 48;
        w_s[c][k] = __ldg(w_hh + (long long)k * G3 + (c >> 4) * H_ + u0 + (c & 15));
    }
    if (tid < 32) len_s[tid] = lengths[b0 + tid];

    float bias[6];
#pragma unroll
    for (int c = 0; c < 6; ++c) {
        int cl = c0 + c;
        bias[c] = b_hh[(cl >> 4) * H_ + u0 + (cl & 15)];
    }

    // zero owned region of h buffer 0
    for (int i = tid; i < 512; i += 256) {
        int r = i >> 4, u = i & 15;
        g_h[0][(b0 + r) * H_ + u0 + u] = 0.f;
    }
    // stage gx for t=0 into buffer 0
    for (int i = tid; i < 1536; i += 256) {
        int r = i / 48, j = i % 48;
        gx_b0[r][j] = __ldg(g_gx + ((long long)(b0 + r) * T_) * G3 +
                            (j >> 4) * H_ + u0 + (j & 15));
    }
    group_sync_(gid);

    for (int t = 0; t < T_; ++t) {
        const int cur = t & 1;
        const float* hc = g_h[cur];
        float* hn = g_h[cur ^ 1];
        float (*gxc)[49] = cur ? gx_b1 : gx_b0;
        float (*gxn)[49] = cur ? gx_b0 : gx_b1;

        // load h tile (cross-SM data -> bypass L1)
        for (int i = tid; i < 2048; i += 256) {
            int r = i >> 6, q = i & 63;
            *reinterpret_cast<float4*>(&h_s[r][q * 4]) =
                __ldcg(reinterpret_cast<const float4*>(hc + (b0 + r) * H_ + q * 4));
        }
        __syncthreads();

        ull acc[6];
#pragma unroll
        for (int c = 0; c < 6; ++c) {
            int cl = c0 + c;
            float add = bias[c] + (cl < 32 ? gxc[lane][cl] : 0.f);
            acc[c] = packf2(add, 0.f);
        }
        const float* hrow = &h_s[lane][0];
        const float* w0   = &w_s[c0][0];
#pragma unroll 4
        for (int k = 0; k < H_; k += 4) {
            ulonglong2 hv = *reinterpret_cast<const ulonglong2*>(hrow + k);
#pragma unroll
            for (int c = 0; c < 6; ++c) {
                ulonglong2 wv = *reinterpret_cast<const ulonglong2*>(w0 + c * 260 + k);
                acc[c] = ffma2(hv.x, wv.x, acc[c]);
                acc[c] = ffma2(hv.y, wv.y, acc[c]);
            }
        }
#pragma unroll
        for (int c = 0; c < 6; ++c) rec_s[lane][c0 + c] = sumf2(acc[c]);
        __syncthreads();

        // gate combine + masked h update
        for (int i = tid; i < 512; i += 256) {
            int r = i >> 4, u = i & 15;
            float z  = sigmoidf_(rec_s[r][u]);          // xz + rz (+bias)
            float rr = sigmoidf_(rec_s[r][16 + u]);     // xr + rr (+bias)
            float hh = tanhf(gxc[r][32 + u] + rr * rec_s[r][32 + u]);
            float ho = h_s[r][u0 + u];
            float hv2 = z * ho + (1.0f - z) * hh;
            hn[(b0 + r) * H_ + u0 + u] = (t < len_s[r]) ? hv2 : ho;
        }
        // prefetch next step's gx BEFORE the barrier (latency hides in wait)
        if (t + 1 < T_) {
            for (int i = tid; i < 1536; i += 256) {
                int r = i / 48, j = i % 48;
                gxn[r][j] = __ldg(g_gx + ((long long)(b0 + r) * T_ + (t + 1)) * G3 +
                                  (j >> 4) * H_ + u0 + (j & 15));
            }
        }
        group_sync_(gid);
    }
    // T_=200 even -> final state in g_h[0]
}

// ---------------- phase 3: logits = h_final @ emb.T ----------------
// CTA = 64 batch rows x 128 vocab, 256 threads, register-tiled (4x8/thread).
__global__ void __launch_bounds__(256) logits_kernel(const float* __restrict__ emb,
                                                     float* __restrict__ out) {
    __shared__ float hs[32][68];    // [k][m]
    __shared__ float es[32][132];   // [k][n]

    const int v0 = blockIdx.x * 128;
    const int b0 = blockIdx.y * 64;
    const int tid = threadIdx.x;
    const int tx = tid & 15, ty = tid >> 4;
    const int n0 = tx * 8, m0 = ty * 4;
    const float* hf = g_h[0];

    ull acc[4][4];
#pragma unroll
    for (int m = 0; m < 4; ++m)
#pragma unroll
        for (int p = 0; p < 4; ++p) acc[m][p] = 0ull;

    for (int kc = 0; kc < 8; ++kc) {
        const int k0 = kc * 32;
        __syncthreads();
        for (int i = tid; i < 512; i += 256) {
            int m = i >> 3, kq = i & 7;
            float4 v = *reinterpret_cast<const float4*>(
                hf + (long long)(b0 + m) * H_ + k0 + kq * 4);
            hs[kq * 4 + 0][m] = v.x; hs[kq * 4 + 1][m] = v.y;
            hs[kq * 4 + 2][m] = v.z; hs[kq * 4 + 3][m] = v.w;
        }
        for (int i = tid; i < 1024; i += 256) {
            int n = i >> 3, kq = i & 7;
            int vg = min(v0 + n, VO - 1);
            float4 e = __ldg(reinterpret_cast<const float4*>(
                emb + (long long)vg * H_ + k0 + kq * 4));
            es[kq * 4 + 0][n] = e.x; es[kq * 4 + 1][n] = e.y;
            es[kq * 4 + 2][n] = e.z; es[kq * 4 + 3][n] = e.w;
        }
        __syncthreads();
#pragma unroll 8
        for (int k = 0; k < 32; ++k) {
            float4 av = *reinterpret_cast<const float4*>(&hs[k][m0]);
            ulonglong2 b01 = *reinterpret_cast<const ulonglong2*>(&es[k][n0]);
            ulonglong2 b23 = *reinterpret_cast<const ulonglong2*>(&es[k][n0 + 4]);
            MICRO_4x8(av, b01, b23, acc);
        }
    }

    // scalar stores (VO odd -> rows only 4B-aligned)
#pragma unroll
    for (int mi = 0; mi < 4; ++mi) {
        float* orow = out + (long long)(b0 + m0 + mi) * VO;
#pragma unroll
        for (int p = 0; p < 4; ++p) {
            float lo, hi; unpackf2(acc[mi][p], lo, hi);
            int v = v0 + n0 + 2 * p;
            if (v < VO)     orow[v]     = lo;
            if (v + 1 < VO) orow[v + 1] = hi;
        }
    }
}

// ---------------- launch ----------------
extern "C" void kernel_launch(void* const* d_in, const int* in_sizes, int n_in,
                              void* d_out, int out_size) {
    const void*  ids     = d_in[0];                  // int64 or int32 [B,T]
    const int*   lengths = (const int*)d_in[1];      // int32 [B]
    const float* emb     = (const float*)d_in[2];    // [V+1, H]
    const float* w_ih    = (const float*)d_in[3];    // [H, 3H]
    const float* w_hh    = (const float*)d_in[4];    // [H, 3H]
    const float* b_ih    = (const float*)d_in[5];    // [3H]
    const float* b_hh    = (const float*)d_in[6];    // [3H]
    float* out = (float*)d_out;

    const int SMEM_REC = (80 * 260 + 3 * 32 * 49) * 4;   // 102,016 B

    cudaFuncSetAttribute(rec_kernel, cudaFuncAttributeMaxDynamicSharedMemorySize, SMEM_REC);

    detect_kernel<<<1, 256>>>((const unsigned*)ids);

    gates_kernel<<<dim3(6, 7, B_), 128>>>(ids, lengths, emb, w_ih, b_ih);

    rec_kernel<<<dim3(16, 8), 256, SMEM_REC>>>(lengths, w_hh, b_hh);

    logits_kernel<<<dim3((VO + 127) / 128, 4), 256>>>(emb, out);
}

// round 16
// speedup vs baseline: 1.4805x; 1.4214x over previous
#include <cuda_runtime.h>
#include <math.h>

// Problem constants
#define B_   256
#define T_   200
#define H_   256
#define G3   768       // 3*H
#define VO   50001     // V+1

typedef unsigned long long ull;

// ---------------- device scratch (no allocs allowed) ----------------
__device__ __align__(16) float g_gx[(size_t)B_ * T_ * G3];  // 157 MB gates_x
__device__ __align__(16) float g_h[2][B_ * H_];             // double-buffered hidden state
__device__ unsigned g_cnt2[8 * 64];               // per-group barrier counters (256B stride)
__device__ unsigned g_gen2[8 * 64];               // per-group generations
__device__ int      g_is64;                       // input_ids dtype flag

// ---------------- packed f32x2 helpers ----------------
__device__ __forceinline__ ull ffma2(ull a, ull b, ull c) {
    ull d;
    asm("fma.rn.f32x2 %0, %1, %2, %3;" : "=l"(d) : "l"(a), "l"(b), "l"(c));
    return d;
}
__device__ __forceinline__ ull packf2(float lo, float hi) {
    ull u;
    asm("mov.b64 %0, {%1, %2};" : "=l"(u) : "f"(lo), "f"(hi));
    return u;
}
__device__ __forceinline__ void unpackf2(ull u, float& lo, float& hi) {
    asm("mov.b64 {%0, %1}, %2;" : "=f"(lo), "=f"(hi) : "l"(u));
}
__device__ __forceinline__ float sumf2(ull u) {
    float lo, hi; unpackf2(u, lo, hi);
    return lo + hi;
}
__device__ __forceinline__ float sigmoidf_(float x) {
    return 1.0f / (1.0f + expf(-x));
}

// ---------------- per-group software barrier (16 CTAs, all resident) --------
__device__ __forceinline__ void group_sync_(int gid) {
    __syncthreads();
    if (threadIdx.x == 0) {
        unsigned* cntp = &g_cnt2[gid * 64];
        volatile unsigned* genp = &g_gen2[gid * 64];
        unsigned gen = *genp;
        __threadfence();
        if (atomicAdd(cntp, 1u) == 15u) {
            *cntp = 0u;
            __threadfence();
            atomicAdd((unsigned*)&g_gen2[gid * 64], 1u);
        } else {
            while (*genp == gen) { }
            __threadfence();
        }
    }
    __syncthreads();
}

// ---------------- dtype detect: int64 vs int32 input_ids ----------------
__global__ void detect_kernel(const unsigned* idw) {
    __shared__ int any;
    if (threadIdx.x == 0) any = 0;
    __syncthreads();
    int local = 0;
    for (int i = threadIdx.x; i < 2048; i += blockDim.x)
        if (idw[2 * i + 1] != 0u) local = 1;
    if (local) atomicOr(&any, 1);
    __syncthreads();
    if (threadIdx.x == 0) g_is64 = (any == 0) ? 1 : 0;
}

// ============================================================================
// 8x8-per-thread GEMM core (32 rows x 256 cols per CTA, 128 threads).
// A staged PRE-DUPLICATED as f32x2 pairs in xs2[k][m]; B staged [k][n] with
// 260-float rows (65 16B-units, odd -> conflict-free LDS.128 streams).
// Lane layout: tx = tid&31 -> cols {tx*4..+3} and {128+tx*4..+3};
//              ty = tid>>5 -> rows ty*8..ty*8+7.  Warp = fixed ty (broadcast A).
// ============================================================================

#define GEMM_CORE(xs2, ws, acc, ty, tx)                                        \
    _Pragma("unroll 8")                                                        \
    for (int k = 0; k < 32; ++k) {                                             \
        const ull* ap_ = &xs2[k][(ty) * 8];                                    \
        ulonglong2 a01_ = *reinterpret_cast<const ulonglong2*>(ap_);           \
        ulonglong2 a23_ = *reinterpret_cast<const ulonglong2*>(ap_ + 2);       \
        ulonglong2 a45_ = *reinterpret_cast<const ulonglong2*>(ap_ + 4);       \
        ulonglong2 a67_ = *reinterpret_cast<const ulonglong2*>(ap_ + 6);       \
        ulonglong2 b0_ = *reinterpret_cast<const ulonglong2*>(&ws[k][(tx)*4]); \
        ulonglong2 b1_ = *reinterpret_cast<const ulonglong2*>(&ws[k][128 + (tx)*4]); \
        ull am_[8] = {a01_.x, a01_.y, a23_.x, a23_.y, a45_.x, a45_.y, a67_.x, a67_.y}; \
        _Pragma("unroll")                                                      \
        for (int m = 0; m < 8; ++m) {                                          \
            acc[m][0] = ffma2(am_[m], b0_.x, acc[m][0]);                       \
            acc[m][1] = ffma2(am_[m], b0_.y, acc[m][1]);                       \
            acc[m][2] = ffma2(am_[m], b1_.x, acc[m][2]);                       \
            acc[m][3] = ffma2(am_[m], b1_.y, acc[m][3]);                       \
        }                                                                      \
    }

// ---------------- phase 1: gates_x = emb[ids] @ w_ih + b_ih ----------------
// CTA = 32 t-rows (one batch element) x 256 gate-cols. grid (3, 7, 256).
__global__ void __launch_bounds__(128) gates_kernel(const void* __restrict__ ids_raw,
                                                    const int* __restrict__ lengths,
                                                    const float* __restrict__ emb,
                                                    const float* __restrict__ w_ih,
                                                    const float* __restrict__ b_ih) {
    __shared__ __align__(16) ull   xs2[32][36];   // [k][m] dup pairs, 9216 B
    __shared__ __align__(16) float ws[32][260];   // [k][n], 33280 B
    __shared__ int ids_s[32];

    const int b   = blockIdx.z;
    const int len = lengths[b];
    const int t0  = blockIdx.y * 32;
    if (t0 >= len) return;
    const int gc0 = blockIdx.x * 256;
    const int tid = threadIdx.x;
    const int is64 = g_is64;

    if (tid < 32) {
        int t = t0 + tid;
        long long id = 0;
        if (t < T_) {
            long long ofs = (long long)b * T_ + t;
            id = is64 ? ((const long long*)ids_raw)[ofs]
                      : (long long)((const int*)ids_raw)[ofs];
        }
        ids_s[tid] = (int)id;
    }

    const int tx = tid & 31, ty = tid >> 5;

    ull acc[8][4];
    {
        float4 bl = __ldg(reinterpret_cast<const float4*>(b_ih + gc0 + tx * 4));
        float4 bh = __ldg(reinterpret_cast<const float4*>(b_ih + gc0 + 128 + tx * 4));
        ull i0 = packf2(bl.x, bl.y), i1 = packf2(bl.z, bl.w);
        ull i2 = packf2(bh.x, bh.y), i3 = packf2(bh.z, bh.w);
#pragma unroll
        for (int m = 0; m < 8; ++m) {
            acc[m][0] = i0; acc[m][1] = i1; acc[m][2] = i2; acc[m][3] = i3;
        }
    }
    __syncthreads();

    for (int kc = 0; kc < 8; ++kc) {
        const int k0 = kc * 32;
        // stage A transposed + duplicated: xs2[k][r] = (a, a)
#pragma unroll
        for (int it = 0; it < 2; ++it) {
            int flat = it * 128 + tid;
            int kq = flat >> 5, r = flat & 31;
            float4 v = __ldg(reinterpret_cast<const float4*>(
                emb + (long long)ids_s[r] * H_ + k0 + kq * 4));
            xs2[kq * 4 + 0][r] = packf2(v.x, v.x);
            xs2[kq * 4 + 1][r] = packf2(v.y, v.y);
            xs2[kq * 4 + 2][r] = packf2(v.z, v.z);
            xs2[kq * 4 + 3][r] = packf2(v.w, v.w);
        }
        // stage B: ws[k][n] = w_ih[(k0+k)*768 + gc0+n]  (n contiguous in gmem)
#pragma unroll
        for (int it = 0; it < 16; ++it) {
            int flat = it * 128 + tid;
            int k = flat >> 6, nq = flat & 63;
            float4 v = __ldg(reinterpret_cast<const float4*>(
                w_ih + (long long)(k0 + k) * G3 + gc0 + nq * 4));
            *reinterpret_cast<float4*>(&ws[k][nq * 4]) = v;
        }
        __syncthreads();

        GEMM_CORE(xs2, ws, acc, ty, tx)

        __syncthreads();
    }

#pragma unroll
    for (int m = 0; m < 8; ++m) {
        int t = t0 + ty * 8 + m;
        if (t < len) {
            float* o = g_gx + ((long long)b * T_ + t) * G3 + gc0;
            ulonglong2 lo, hi;
            lo.x = acc[m][0]; lo.y = acc[m][1];
            hi.x = acc[m][2]; hi.y = acc[m][3];
            *reinterpret_cast<ulonglong2*>(o + tx * 4)       = lo;
            *reinterpret_cast<ulonglong2*>(o + 128 + tx * 4) = hi;
        }
    }
}

// ---------------- phase 2: persistent GRU recurrence ----------------
// grid = (16 unit tiles x 8 batch groups) = 128 CTAs, 256 threads (8 warps,
// 6 cols each). Per-GROUP barrier (16 CTAs). gx double-buffered in SMEM
// (row stride 52 floats = 208 B -> every gate*16+q*4 offset is 16B-aligned).
__global__ void __launch_bounds__(256, 1) rec_kernel(const int* __restrict__ lengths,
                                                     const float* __restrict__ w_hh,
                                                     const float* __restrict__ b_hh) {
    extern __shared__ float sm[];
    float (*w_s)[260]  = (float(*)[260])sm;                           // 48 x 260
    float (*h_s)[260]  = (float(*)[260])(sm + 48 * 260);              // 32 x 260
    float (*rec_s)[49] = (float(*)[49]) (sm + 80 * 260);              // 32 x 49
    float (*gx_b0)[52] = (float(*)[52]) (sm + 80 * 260 + 32 * 49);    // 32 x 52
    float (*gx_b1)[52] = (float(*)[52]) (sm + 80 * 260 + 32 * 49 + 32 * 52);
    __shared__ int len_s[32];

    const int u0  = blockIdx.x * 16;
    const int b0  = blockIdx.y * 32;
    const int gid = blockIdx.y;
    const int tid = threadIdx.x;
    const int lane = tid & 31, wp = tid >> 5;   // 8 warps
    const int c0 = wp * 6;                      // 6 cols per warp

    // persistent weight slice: w_s[c][k] = w_hh[k*768 + gate*256 + u0 + u]
    for (int i = tid; i < 48 * H_; i += 256) {
        int c = i % 48, k = i / 48;
        w_s[c][k] = __ldg(w_hh + (long long)k * G3 + (c >> 4) * H_ + u0 + (c & 15));
    }
    if (tid < 32) len_s[tid] = lengths[b0 + tid];

    float bias[6];
#pragma unroll
    for (int c = 0; c < 6; ++c) {
        int cl = c0 + c;
        bias[c] = b_hh[(cl >> 4) * H_ + u0 + (cl & 15)];
    }

    // zero owned region of h buffer 0
    for (int i = tid; i < 512; i += 256) {
        int r = i >> 4, u = i & 15;
        g_h[0][(b0 + r) * H_ + u0 + u] = 0.f;
    }
    // stage gx for t=0 into buffer 0 (vectorized, 16B-aligned rows)
#pragma unroll
    for (int it = 0; it < 2; ++it) {
        int i = it * 256 + tid;
        int r = i >> 4, s = i & 15;
        if (s < 12) {
            int gate = s >> 2, q = s & 3;
            float4 v = __ldg(reinterpret_cast<const float4*>(
                g_gx + ((long long)(b0 + r) * T_) * G3 + gate * H_ + u0 + q * 4));
            *reinterpret_cast<float4*>(&gx_b0[r][gate * 16 + q * 4]) = v;
        }
    }
    group_sync_(gid);

    for (int t = 0; t < T_; ++t) {
        const int cur = t & 1;
        const float* hc = g_h[cur];
        float* hn = g_h[cur ^ 1];
        float (*gxc)[52] = cur ? gx_b1 : gx_b0;
        float (*gxn)[52] = cur ? gx_b0 : gx_b1;

        // load h tile: batch all 8 LDG.128.cg first (MLP=8), then STS
        float4 hb[8];
#pragma unroll
        for (int j = 0; j < 8; ++j) {
            int i = tid + j * 256;
            int r = i >> 6, q = i & 63;
            hb[j] = __ldcg(reinterpret_cast<const float4*>(hc + (b0 + r) * H_ + q * 4));
        }
#pragma unroll
        for (int j = 0; j < 8; ++j) {
            int i = tid + j * 256;
            int r = i >> 6, q = i & 63;
            *reinterpret_cast<float4*>(&h_s[r][q * 4]) = hb[j];
        }
        __syncthreads();

        ull acc[6];
#pragma unroll
        for (int c = 0; c < 6; ++c) {
            int cl = c0 + c;
            float add = bias[c] + (cl < 32 ? gxc[lane][cl] : 0.f);
            acc[c] = packf2(add, 0.f);
        }
        const float* hrow = &h_s[lane][0];
        const float* w0   = &w_s[c0][0];
#pragma unroll 4
        for (int k = 0; k < H_; k += 8) {
            ulonglong2 h01 = *reinterpret_cast<const ulonglong2*>(hrow + k);
            ulonglong2 h23 = *reinterpret_cast<const ulonglong2*>(hrow + k + 4);
#pragma unroll
            for (int c = 0; c < 6; ++c) {
                const float* wr = w0 + c * 260 + k;
                ulonglong2 w01 = *reinterpret_cast<const ulonglong2*>(wr);
                ulonglong2 w23 = *reinterpret_cast<const ulonglong2*>(wr + 4);
                acc[c] = ffma2(h01.x, w01.x, acc[c]);
                acc[c] = ffma2(h01.y, w01.y, acc[c]);
                acc[c] = ffma2(h23.x, w23.x, acc[c]);
                acc[c] = ffma2(h23.y, w23.y, acc[c]);
            }
        }
#pragma unroll
        for (int c = 0; c < 6; ++c) rec_s[lane][c0 + c] = sumf2(acc[c]);
        __syncthreads();

        // gate combine + masked h update
        for (int i = tid; i < 512; i += 256) {
            int r = i >> 4, u = i & 15;
            float z  = sigmoidf_(rec_s[r][u]);          // xz + rz (+bias)
            float rr = sigmoidf_(rec_s[r][16 + u]);     // xr + rr (+bias)
            float hh = tanhf(gxc[r][32 + u] + rr * rec_s[r][32 + u]);
            float ho = h_s[r][u0 + u];
            float hv2 = z * ho + (1.0f - z) * hh;
            hn[(b0 + r) * H_ + u0 + u] = (t < len_s[r]) ? hv2 : ho;
        }
        // prefetch next step's gx BEFORE the barrier (latency hides in wait)
        if (t + 1 < T_) {
#pragma unroll
            for (int it = 0; it < 2; ++it) {
                int i = it * 256 + tid;
                int r = i >> 4, s = i & 15;
                if (s < 12) {
                    int gate = s >> 2, q = s & 3;
                    float4 v = __ldg(reinterpret_cast<const float4*>(
                        g_gx + ((long long)(b0 + r) * T_ + (t + 1)) * G3 +
                        gate * H_ + u0 + q * 4));
                    *reinterpret_cast<float4*>(&gxn[r][gate * 16 + q * 4]) = v;
                }
            }
        }
        group_sync_(gid);
    }
    // T_=200 even -> final state in g_h[0]
}

// ---------------- phase 3: logits = h_final @ emb.T ----------------
// CTA = 32 batch rows x 256 vocab cols, 128 threads. grid (8, 196):
// x = batch tile (fastest) so the 8 CTAs sharing an emb tile are adjacent.
__global__ void __launch_bounds__(128) logits_kernel(const float* __restrict__ emb,
                                                     float* __restrict__ out) {
    __shared__ __align__(16) ull   hs2[32][36];   // [k][m] dup pairs
    __shared__ __align__(16) float es[32][260];   // [k][n]

    const int b0 = blockIdx.x * 32;
    const int v0 = blockIdx.y * 256;
    const int tid = threadIdx.x;
    const int tx = tid & 31, ty = tid >> 5;
    const float* hf = g_h[0];

    ull acc[8][4];
#pragma unroll
    for (int m = 0; m < 8; ++m)
#pragma unroll
        for (int q = 0; q < 4; ++q) acc[m][q] = 0ull;

    for (int kc = 0; kc < 8; ++kc) {
        const int k0 = kc * 32;
        if (kc) __syncthreads();
        // stage h transposed + duplicated
#pragma unroll
        for (int it = 0; it < 2; ++it) {
            int flat = it * 128 + tid;
            int kq = flat >> 5, r = flat & 31;
            float4 v = *reinterpret_cast<const float4*>(
                hf + (long long)(b0 + r) * H_ + k0 + kq * 4);
            hs2[kq * 4 + 0][r] = packf2(v.x, v.x);
            hs2[kq * 4 + 1][r] = packf2(v.y, v.y);
            hs2[kq * 4 + 2][r] = packf2(v.z, v.z);
            hs2[kq * 4 + 3][r] = packf2(v.w, v.w);
        }
        // stage emb tile transposed: es[k][n] = emb[v0+n][k0+k]
#pragma unroll
        for (int it = 0; it < 16; ++it) {
            int flat = it * 128 + tid;
            int kq = flat >> 8, n = flat & 255;
            int vg = min(v0 + n, VO - 1);
            float4 v = __ldg(reinterpret_cast<const float4*>(
                emb + (long long)vg * H_ + k0 + kq * 4));
            es[kq * 4 + 0][n] = v.x;
            es[kq * 4 + 1][n] = v.y;
            es[kq * 4 + 2][n] = v.z;
            es[kq * 4 + 3][n] = v.w;
        }
        __syncthreads();

        GEMM_CORE(hs2, es, acc, ty, tx)
    }

    // scalar stores (VO odd -> rows only 4B-aligned)
#pragma unroll
    for (int m = 0; m < 8; ++m) {
        float* orow = out + (long long)(b0 + ty * 8 + m) * VO;
#pragma unroll
        for (int q = 0; q < 4; ++q) {
            float lo, hi; unpackf2(acc[m][q], lo, hi);
            int v = v0 + ((q < 2) ? (tx * 4 + 2 * q) : (128 + tx * 4 + 2 * (q - 2)));
            if (v < VO)     orow[v]     = lo;
            if (v + 1 < VO) orow[v + 1] = hi;
        }
    }
}

// ---------------- launch ----------------
extern "C" void kernel_launch(void* const* d_in, const int* in_sizes, int n_in,
                              void* d_out, int out_size) {
    const void*  ids     = d_in[0];                  // int64 or int32 [B,T]
    const int*   lengths = (const int*)d_in[1];      // int32 [B]
    const float* emb     = (const float*)d_in[2];    // [V+1, H]
    const float* w_ih    = (const float*)d_in[3];    // [H, 3H]
    const float* w_hh    = (const float*)d_in[4];    // [H, 3H]
    const float* b_ih    = (const float*)d_in[5];    // [3H]
    const float* b_hh    = (const float*)d_in[6];    // [3H]
    float* out = (float*)d_out;

    const int SMEM_REC = (80 * 260 + 32 * 49 + 2 * 32 * 52) * 4;   // 102,784 B

    cudaFuncSetAttribute(rec_kernel, cudaFuncAttributeMaxDynamicSharedMemorySize, SMEM_REC);

    detect_kernel<<<1, 256>>>((const unsigned*)ids);

    gates_kernel<<<dim3(3, 7, B_), 128>>>(ids, lengths, emb, w_ih, b_ih);

    rec_kernel<<<dim3(16, 8), 256, SMEM_REC>>>(lengths, w_hh, b_hh);

    logits_kernel<<<dim3(8, 196), 128>>>(emb, out);
}